// round 2
// baseline (speedup 1.0000x reference)
#include <cuda_runtime.h>
#include <math.h>

#define BSZ 1024

// ---------------- scratch (device globals; no allocations allowed) ----------------
__device__ float g_X1[BSZ*128];     // [t, x_gene] grn input
__device__ float g_XB[BSZ*129];     // [t, x] b-net input
__device__ float g_h1[BSZ*1024];
__device__ float g_d1[BSZ*1024];
__device__ float g_h2[BSZ*960];
__device__ float g_d2[BSZ*960];
__device__ float g_h3[BSZ*896];
__device__ float g_d3[BSZ*896];
__device__ float g_e1[BSZ*512];
__device__ float g_e2[BSZ*448];
__device__ float g_gv[BSZ];
__device__ float g_tr[BSZ];

// ---------------- prep: build inputs, zero trace accumulators ----------------
__global__ void prep_kernel(const float* __restrict__ pt, const float* __restrict__ x)
{
    int b = blockIdx.x;
    int t = threadIdx.x;
    float tv = pt[0];
    if (t == 0){ g_X1[b*128] = tv; g_XB[b*129] = tv; g_tr[b] = 0.f; }
    for (int c = t; c < 128; c += blockDim.x){
        float xv = x[b*128 + c];
        if (c < 127) g_X1[b*128 + 1 + c] = xv;
        g_XB[b*129 + 1 + c] = xv;
    }
}

// ---------------- generic fp32 GEMM: C = act(A @ W + bias), M=1024 ----------------
// A: [1024 x K] (lda), W: [K x N] row-major, tile 64x64, BK=16, 256 threads (4x4/thread)
template<bool TANH>
__global__ __launch_bounds__(256)
void fwd_gemm(const float* __restrict__ A, int lda,
              const float* __restrict__ W,
              const float* __restrict__ bias,
              float* __restrict__ H, float* __restrict__ Dm,
              int N, int K)
{
    __shared__ float sA[16*65];   // [k][m] transposed, padded
    __shared__ float sB[16*64];   // [k][n]
    int n0 = blockIdx.x * 64;
    int m0 = blockIdx.y * 64;
    int tid = threadIdx.x;
    int tx = tid & 15, ty = tid >> 4;
    float acc[4][4] = {};
    for (int k0 = 0; k0 < K; k0 += 16){
        #pragma unroll
        for (int e = 0; e < 4; e++){
            int id = tid + e*256;
            int m = id >> 4, k = id & 15;
            sA[k*65 + m] = (k0 + k < K) ? A[(m0+m)*lda + k0 + k] : 0.f;
        }
        #pragma unroll
        for (int e = 0; e < 4; e++){
            int id = tid + e*256;
            int kb = id >> 6, n = id & 63;
            sB[kb*64 + n] = (k0 + kb < K) ? W[(k0+kb)*N + n0 + n] : 0.f;
        }
        __syncthreads();
        #pragma unroll
        for (int kk = 0; kk < 16; kk++){
            float a[4], bb[4];
            #pragma unroll
            for (int r = 0; r < 4; r++) a[r] = sA[kk*65 + ty*4 + r];
            #pragma unroll
            for (int c = 0; c < 4; c++) bb[c] = sB[kk*64 + tx*4 + c];
            #pragma unroll
            for (int r = 0; r < 4; r++)
                #pragma unroll
                for (int c = 0; c < 4; c++)
                    acc[r][c] += a[r]*bb[c];
        }
        __syncthreads();
    }
    #pragma unroll
    for (int r = 0; r < 4; r++){
        int m = m0 + ty*4 + r;
        #pragma unroll
        for (int c = 0; c < 4; c++){
            int n = n0 + tx*4 + c;
            float v = acc[r][c] + bias[n];
            if (TANH){
                float h = tanhf(v);
                H[m*N + n] = h;
                if (Dm) Dm[m*N + n] = 1.f - h*h;
            } else {
                H[m*N + n] = v;
            }
        }
    }
}

// ---------------- b-net head: g[b] = e2[b] . bdw + bdb ----------------
__global__ void bnet_head(const float* __restrict__ bdw, const float* __restrict__ bdb,
                          float* __restrict__ out_g)
{
    int b = blockIdx.x;
    int t = threadIdx.x; // 128
    float s = 0.f;
    for (int k = t; k < 448; k += 128) s += g_e2[b*448 + k] * bdw[k];
    #pragma unroll
    for (int off = 16; off > 0; off >>= 1) s += __shfl_xor_sync(0xffffffffu, s, off);
    __shared__ float sw[4];
    if ((t & 31) == 0) sw[t >> 5] = s;
    __syncthreads();
    if (t == 0){
        float g = sw[0] + sw[1] + sw[2] + sw[3] + bdb[0];
        g_gv[b] = g;
        out_g[b] = g;
    }
}

// ---------------- Jacobian trace: fused per-sample meet-in-the-middle ----------------
// CTA = (sample b, k-tile kt of 64 cols of the 960-dim hidden-2 index).
// GEMM1: L[i,k]  = sum_j W0[i+1,j]*d1[j]*W1[j,kt+k]      (128x64, K=1024)
// GEMM2: R[k,i]  = sum_l W2[kt+k,l]*d3[l]*Wd[l,i]         (64x128, K=896)
// partial tr    += sum_{i,k} L[i,k]*d2[kt+k]*R[k,i]
#define TKJ 64
__global__ __launch_bounds__(256)
void jac_kernel(const float* __restrict__ gw0,
                const float* __restrict__ gw1,
                const float* __restrict__ gw2,
                const float* __restrict__ gdw)
{
    __shared__ __align__(16) float sbuf[128*17 + 16*64];  // gemm1: A[128][17] + B[16][64]; gemm2 aliases
    __shared__ float sLt[128*65];                          // L * d2, [i][k], padded
    __shared__ float sd2[TKJ];
    __shared__ float swarp[8];
    int b  = blockIdx.x;
    int kt = blockIdx.y * TKJ;
    int tid = threadIdx.x;

    if (tid < TKJ) sd2[tid] = g_d2[b*960 + kt + tid];

    // ---- GEMM1 ----
    {
        float* sA = sbuf;             // [128][17]  raw W0 rows (i -> W0 row i+1; i=127 -> 0)
        float* sB = sbuf + 128*17;    // [16][64]   W1 rows scaled by d1[j]
        int tx = tid & 15, ty = tid >> 4;           // thread tile: rows i=ty*8..+7, cols k=tx*4..+3
        float acc[8][4] = {};
        int ai  = tid >> 1;           // 0..127
        int ac0 = (tid & 1) * 8;
        int bj  = tid >> 4;           // 0..15
        int bk4 = (tid & 15) * 4;
        for (int j0 = 0; j0 < 1024; j0 += 16){
            #pragma unroll
            for (int e = 0; e < 8; e++)
                sA[ai*17 + ac0 + e] = (ai < 127) ? gw0[(ai+1)*1024 + j0 + ac0 + e] : 0.f;
            {
                float d1v = g_d1[b*1024 + j0 + bj];
                float4 v = *(const float4*)&gw1[(j0+bj)*960 + kt + bk4];
                float* dst = &sB[bj*64 + bk4];
                dst[0]=v.x*d1v; dst[1]=v.y*d1v; dst[2]=v.z*d1v; dst[3]=v.w*d1v;
            }
            __syncthreads();
            #pragma unroll
            for (int jj = 0; jj < 16; jj++){
                float a[8];
                #pragma unroll
                for (int r = 0; r < 8; r++) a[r] = sA[(ty*8+r)*17 + jj];
                float4 b4 = *(const float4*)&sB[jj*64 + tx*4];
                #pragma unroll
                for (int r = 0; r < 8; r++){
                    acc[r][0] += a[r]*b4.x; acc[r][1] += a[r]*b4.y;
                    acc[r][2] += a[r]*b4.z; acc[r][3] += a[r]*b4.w;
                }
            }
            __syncthreads();
        }
        #pragma unroll
        for (int r = 0; r < 8; r++)
            #pragma unroll
            for (int c = 0; c < 4; c++)
                sLt[(ty*8+r)*65 + tx*4 + c] = acc[r][c] * sd2[tx*4 + c];
        __syncthreads();
    }

    // ---- GEMM2 + fused reduction ----
    float partial = 0.f;
    {
        float* sA2 = sbuf;            // [64][17]  W2 tile rows (k)
        float* sB2 = sbuf + 64*17;    // [16][128] Wd rows scaled by d3[l]
        int tx2 = tid & 15;           // i = tx2*8..+7
        int ty2 = tid >> 4;           // k = ty2*4..+3
        float acc2[4][8] = {};
        int ak  = tid >> 2;           // 0..63
        int ac0 = (tid & 3) * 4;
        int bl  = tid >> 4;           // 0..15
        int bi0 = (tid & 15) * 8;
        for (int l0 = 0; l0 < 896; l0 += 16){
            {
                float4 v = *(const float4*)&gw2[(kt+ak)*896 + l0 + ac0];
                float* dst = &sA2[ak*17 + ac0];
                dst[0]=v.x; dst[1]=v.y; dst[2]=v.z; dst[3]=v.w;
            }
            {
                float d3v = g_d3[b*896 + l0 + bl];
                const float4* src = (const float4*)&gdw[(l0+bl)*128 + bi0];
                float4 v0 = src[0], v1 = src[1];
                float* dst = &sB2[bl*128 + bi0];
                dst[0]=v0.x*d3v; dst[1]=v0.y*d3v; dst[2]=v0.z*d3v; dst[3]=v0.w*d3v;
                dst[4]=v1.x*d3v; dst[5]=v1.y*d3v; dst[6]=v1.z*d3v; dst[7]=v1.w*d3v;
            }
            __syncthreads();
            #pragma unroll
            for (int ll = 0; ll < 16; ll++){
                float a[4];
                #pragma unroll
                for (int r = 0; r < 4; r++) a[r] = sA2[(ty2*4+r)*17 + ll];
                float4 v0 = *(const float4*)&sB2[ll*128 + tx2*8];
                float4 v1 = *(const float4*)&sB2[ll*128 + tx2*8 + 4];
                #pragma unroll
                for (int r = 0; r < 4; r++){
                    acc2[r][0] += a[r]*v0.x; acc2[r][1] += a[r]*v0.y;
                    acc2[r][2] += a[r]*v0.z; acc2[r][3] += a[r]*v0.w;
                    acc2[r][4] += a[r]*v1.x; acc2[r][5] += a[r]*v1.y;
                    acc2[r][6] += a[r]*v1.z; acc2[r][7] += a[r]*v1.w;
                }
            }
            __syncthreads();
        }
        // tr partial: acc2[r][c] is R[k=ty2*4+r][i=tx2*8+c]; pair with sLt[i][k] (d2 folded).
        // Row i=127 of L is exactly zero, so the out-of-range trace term vanishes.
        #pragma unroll
        for (int r = 0; r < 4; r++)
            #pragma unroll
            for (int c = 0; c < 8; c++)
                partial += acc2[r][c] * sLt[(tx2*8 + c)*65 + ty2*4 + r];
    }
    #pragma unroll
    for (int off = 16; off > 0; off >>= 1)
        partial += __shfl_xor_sync(0xffffffffu, partial, off);
    if ((tid & 31) == 0) swarp[tid >> 5] = partial;
    __syncthreads();
    if (tid == 0){
        float s = 0.f;
        #pragma unroll
        for (int w = 0; w < 8; w++) s += swarp[w];
        atomicAdd(&g_tr[b], s);
    }
}

// ---------------- finalize: dp_dt = g - p * tr ----------------
__global__ void fin_kernel(const float* __restrict__ p, float* __restrict__ out_dp)
{
    int b = blockIdx.x * blockDim.x + threadIdx.x;
    if (b < BSZ) out_dp[b] = g_gv[b] - p[b] * g_tr[b];
}

// ---------------- launch ----------------
extern "C" void kernel_launch(void* const* d_in, const int* in_sizes, int n_in,
                              void* d_out, int out_size)
{
    const float* pt  = (const float*)d_in[0];
    const float* x   = (const float*)d_in[1];
    // d_in[2] = g_x (unused by reference)
    const float* p   = (const float*)d_in[3];
    const float* gw0 = (const float*)d_in[4];
    const float* gb0 = (const float*)d_in[5];
    const float* gw1 = (const float*)d_in[6];
    const float* gb1 = (const float*)d_in[7];
    const float* gw2 = (const float*)d_in[8];
    const float* gb2 = (const float*)d_in[9];
    const float* gdw = (const float*)d_in[10];
    const float* gdb = (const float*)d_in[11];
    const float* bw0 = (const float*)d_in[12];
    const float* bb0 = (const float*)d_in[13];
    const float* bw1 = (const float*)d_in[14];
    const float* bb1 = (const float*)d_in[15];
    const float* bdw = (const float*)d_in[16];
    const float* bdb = (const float*)d_in[17];
    float* out = (float*)d_out;

    float *pX1, *pXB, *ph1, *pd1, *ph2, *pd2, *ph3, *pd3, *pe1, *pe2;
    cudaGetSymbolAddress((void**)&pX1, g_X1);
    cudaGetSymbolAddress((void**)&pXB, g_XB);
    cudaGetSymbolAddress((void**)&ph1, g_h1);
    cudaGetSymbolAddress((void**)&pd1, g_d1);
    cudaGetSymbolAddress((void**)&ph2, g_h2);
    cudaGetSymbolAddress((void**)&pd2, g_d2);
    cudaGetSymbolAddress((void**)&ph3, g_h3);
    cudaGetSymbolAddress((void**)&pd3, g_d3);
    cudaGetSymbolAddress((void**)&pe1, g_e1);
    cudaGetSymbolAddress((void**)&pe2, g_e2);

    prep_kernel<<<BSZ, 256>>>(pt, x);
    // grn forward (stores h and d = 1 - h^2)
    fwd_gemm<true ><<<dim3(16, 16), 256>>>(pX1, 128,  gw0, gb0, ph1, pd1, 1024, 128);
    fwd_gemm<true ><<<dim3(15, 16), 256>>>(ph1, 1024, gw1, gb1, ph2, pd2, 960,  1024);
    fwd_gemm<true ><<<dim3(14, 16), 256>>>(ph2, 960,  gw2, gb2, ph3, pd3, 896,  960);
    fwd_gemm<false><<<dim3(2,  16), 256>>>(ph3, 896,  gdw, gdb, out, nullptr, 128, 896);
    // b-net forward
    fwd_gemm<true ><<<dim3(8,  16), 256>>>(pXB, 129,  bw0, bb0, pe1, nullptr, 512, 129);
    fwd_gemm<true ><<<dim3(7,  16), 256>>>(pe1, 512,  bw1, bb1, pe2, nullptr, 448, 512);
    bnet_head<<<BSZ, 128>>>(bdw, bdb, out + BSZ*128);
    // Jacobian trace (dominant cost)
    jac_kernel<<<dim3(BSZ, 15), 256>>>(gw0, gw1, gw2, gdw);
    fin_kernel<<<4, 256>>>(p, out + BSZ*128 + BSZ);
}

// round 4
// speedup vs baseline: 1.5514x; 1.5514x over previous
#include <cuda_runtime.h>
#include <math.h>

#define BSZ 1024

// ---------------- scratch (device globals; no allocations allowed) ----------------
__device__ float g_X1[BSZ*128];     // [t, x_gene] grn input
__device__ float g_XB[BSZ*129];     // [t, x] b-net input
__device__ float g_h1[BSZ*1024];
__device__ float g_d1[BSZ*1024];
__device__ float g_h2[BSZ*960];
__device__ float g_d2[BSZ*960];
__device__ float g_h3[BSZ*896];
__device__ float g_d3[BSZ*896];
__device__ float g_e1[BSZ*512];
__device__ float g_e2[BSZ*448];
__device__ float g_gv[BSZ];
__device__ float g_tr[BSZ];

// ---------------- packed f32x2 helpers (FFMA2: 2 fp32 MACs per fma-pipe slot) ----
// NOTE: "l" asm constraint binds 64-bit INTEGER regs — carry packed pair as u64.
typedef unsigned long long u64;
__device__ __forceinline__ u64 fma2(u64 a, u64 b, u64 c){
    u64 d; asm("fma.rn.f32x2 %0, %1, %2, %3;" : "=l"(d) : "l"(a), "l"(b), "l"(c)); return d;
}
__device__ __forceinline__ u64 mul2(u64 a, u64 b){
    u64 d; asm("mul.rn.f32x2 %0, %1, %2;" : "=l"(d) : "l"(a), "l"(b)); return d;
}
__device__ __forceinline__ u64 pack2(float lo, float hi){
    u64 d; asm("mov.b64 %0, {%1, %2};" : "=l"(d) : "f"(lo), "f"(hi)); return d;
}
__device__ __forceinline__ float2 unpack2(u64 d){
    float2 v; asm("mov.b64 {%0, %1}, %2;" : "=f"(v.x), "=f"(v.y) : "l"(d)); return v;
}

// ---------------- prep: build inputs, zero trace accumulators ----------------
__global__ void prep_kernel(const float* __restrict__ pt, const float* __restrict__ x)
{
    int b = blockIdx.x;
    int t = threadIdx.x;
    float tv = pt[0];
    if (t == 0){ g_X1[b*128] = tv; g_XB[b*129] = tv; g_tr[b] = 0.f; }
    for (int c = t; c < 128; c += blockDim.x){
        float xv = x[b*128 + c];
        if (c < 127) g_X1[b*128 + 1 + c] = xv;
        g_XB[b*129 + 1 + c] = xv;
    }
}

// ---------------- generic fp32 GEMM: C = act(A @ W + bias), M=1024 ----------------
template<bool TANH>
__global__ __launch_bounds__(256)
void fwd_gemm(const float* __restrict__ A, int lda,
              const float* __restrict__ W,
              const float* __restrict__ bias,
              float* __restrict__ H, float* __restrict__ Dm,
              int N, int K)
{
    __shared__ float sA[16*65];   // [k][m] transposed, padded
    __shared__ float sB[16*64];   // [k][n]
    int n0 = blockIdx.x * 64;
    int m0 = blockIdx.y * 64;
    int tid = threadIdx.x;
    int tx = tid & 15, ty = tid >> 4;
    float acc[4][4] = {};
    for (int k0 = 0; k0 < K; k0 += 16){
        #pragma unroll
        for (int e = 0; e < 4; e++){
            int id = tid + e*256;
            int m = id >> 4, k = id & 15;
            sA[k*65 + m] = (k0 + k < K) ? A[(m0+m)*lda + k0 + k] : 0.f;
        }
        #pragma unroll
        for (int e = 0; e < 4; e++){
            int id = tid + e*256;
            int kb = id >> 6, n = id & 63;
            sB[kb*64 + n] = (k0 + kb < K) ? W[(k0+kb)*N + n0 + n] : 0.f;
        }
        __syncthreads();
        #pragma unroll
        for (int kk = 0; kk < 16; kk++){
            float a[4], bb[4];
            #pragma unroll
            for (int r = 0; r < 4; r++) a[r] = sA[kk*65 + ty*4 + r];
            #pragma unroll
            for (int c = 0; c < 4; c++) bb[c] = sB[kk*64 + tx*4 + c];
            #pragma unroll
            for (int r = 0; r < 4; r++)
                #pragma unroll
                for (int c = 0; c < 4; c++)
                    acc[r][c] += a[r]*bb[c];
        }
        __syncthreads();
    }
    #pragma unroll
    for (int r = 0; r < 4; r++){
        int m = m0 + ty*4 + r;
        #pragma unroll
        for (int c = 0; c < 4; c++){
            int n = n0 + tx*4 + c;
            float v = acc[r][c] + bias[n];
            if (TANH){
                float h = tanhf(v);
                H[m*N + n] = h;
                if (Dm) Dm[m*N + n] = 1.f - h*h;
            } else {
                H[m*N + n] = v;
            }
        }
    }
}

// ---------------- b-net head: g[b] = e2[b] . bdw + bdb ----------------
__global__ void bnet_head(const float* __restrict__ bdw, const float* __restrict__ bdb,
                          float* __restrict__ out_g)
{
    int b = blockIdx.x;
    int t = threadIdx.x; // 128
    float s = 0.f;
    for (int k = t; k < 448; k += 128) s += g_e2[b*448 + k] * bdw[k];
    #pragma unroll
    for (int off = 16; off > 0; off >>= 1) s += __shfl_xor_sync(0xffffffffu, s, off);
    __shared__ float sw[4];
    if ((t & 31) == 0) sw[t >> 5] = s;
    __syncthreads();
    if (t == 0){
        float g = sw[0] + sw[1] + sw[2] + sw[3] + bdb[0];
        g_gv[b] = g;
        out_g[b] = g;
    }
}

// ---------------- Jacobian trace: 2-sample packed-f32x2 meet-in-the-middle ----------------
// CTA = (sample pair (2b,2b+1), k-tile kt of 64 over the 960 hidden-2 dim).
// GEMM1: L_s[i,k] = sum_j W0[i+1,j]*d1_s[j]*W1[j,kt+k]   (128x64, K=1024)
// GEMM2: R_s[k,i] = sum_l W2[kt+k,l]*d3_s[l]*Wd[l,i]     (64x128, K=896)
// tr_s partial  += sum_{i,k} L_s[i,k]*d2_s[kt+k]*R_s[k,i]
// Samples A/B ride the two lanes of every f32x2.
#define TKJ 64
#define JCH 32  // k-chunk depth for both contractions

// smem layout (bytes):
//   sLp   : [128][68] u64  = 69632
//   union : GEMM1 (sW0t [32][132] f32 = 16896, sW1p [32][64] u64 = 16384) = 33280
//           GEMM2 (sW2t [32][68]  f32 =  8704, sWdp [32][128] u64 = 32768) = 41472
//   sd2p  : 64 u64 = 512 ; swp : 8 u64 = 64
#define SMEM_JAC (69632 + 41472 + 576)

__global__ __launch_bounds__(256)
void jac2_kernel(const float* __restrict__ gw0,
                 const float* __restrict__ gw1,
                 const float* __restrict__ gw2,
                 const float* __restrict__ gdw)
{
    extern __shared__ __align__(16) char smem_raw[];
    u64*   sLp  = (u64*)smem_raw;                       // [i][k] stride 68, packed {A,B}
    float* sU   = (float*)(smem_raw + 69632);
    u64*   sdp  = (u64*)(smem_raw + 69632 + 41472);
    u64*   sd2p = sdp;        // 64
    u64*   swp  = sdp + 64;   // 8

    int bA = blockIdx.x * 2, bB = bA + 1;
    int kt = blockIdx.y * TKJ;
    int tid = threadIdx.x;
    int tx = tid & 15, ty = tid >> 4;

    if (tid < TKJ)
        sd2p[tid] = pack2(g_d2[bA*960 + kt + tid], g_d2[bB*960 + kt + tid]);

    // ================= GEMM1 =================
    {
        float* sW0t = sU;                    // [j][i] stride 132
        u64*   sW1p = (u64*)(sU + JCH*132);  // [j][k] packed, stride 64

        u64 acc[8][4];
        #pragma unroll
        for (int r = 0; r < 8; r++)
            #pragma unroll
            for (int c = 0; c < 4; c++) acc[r][c] = 0ull;

        int fi = tid >> 1;           // i 0..127
        int fj = (tid & 1) * 16;     // j base
        int wj = tid >> 3;           // j 0..31
        int wk = (tid & 7) * 8;      // k base

        for (int j0 = 0; j0 < 1024; j0 += JCH){
            __syncthreads();
            // W0 tile, transposed: sW0t[j][i] = W0[i+1][j0+j]; row i=127 -> 0
            if (fi < 127){
                const float* src = &gw0[(fi+1)*1024 + j0 + fj];
                #pragma unroll
                for (int q = 0; q < 4; q++){
                    float4 v = *(const float4*)(src + q*4);
                    sW0t[(fj+q*4+0)*132 + fi] = v.x;
                    sW0t[(fj+q*4+1)*132 + fi] = v.y;
                    sW0t[(fj+q*4+2)*132 + fi] = v.z;
                    sW0t[(fj+q*4+3)*132 + fi] = v.w;
                }
            } else {
                #pragma unroll
                for (int q = 0; q < 16; q++) sW0t[(fj+q)*132 + fi] = 0.f;
            }
            // W1 tile with d1 folded, packed per sample pair
            {
                u64 d1p = pack2(g_d1[bA*1024 + j0 + wj], g_d1[bB*1024 + j0 + wj]);
                const float* src = &gw1[(j0+wj)*960 + kt + wk];
                float4 v0 = *(const float4*)src;
                float4 v1 = *(const float4*)(src + 4);
                u64* dst = &sW1p[wj*64 + wk];
                dst[0] = mul2(pack2(v0.x, v0.x), d1p);
                dst[1] = mul2(pack2(v0.y, v0.y), d1p);
                dst[2] = mul2(pack2(v0.z, v0.z), d1p);
                dst[3] = mul2(pack2(v0.w, v0.w), d1p);
                dst[4] = mul2(pack2(v1.x, v1.x), d1p);
                dst[5] = mul2(pack2(v1.y, v1.y), d1p);
                dst[6] = mul2(pack2(v1.z, v1.z), d1p);
                dst[7] = mul2(pack2(v1.w, v1.w), d1p);
            }
            __syncthreads();
            #pragma unroll 8
            for (int jj = 0; jj < JCH; jj++){
                float4 a0 = *(const float4*)&sW0t[jj*132 + ty*8];
                float4 a1 = *(const float4*)&sW0t[jj*132 + ty*8 + 4];
                const u64* bpp = &sW1p[jj*64 + tx*4];
                u64 b0 = bpp[0], b1 = bpp[1], b2 = bpp[2], b3 = bpp[3];
                float a[8] = {a0.x, a0.y, a0.z, a0.w, a1.x, a1.y, a1.z, a1.w};
                #pragma unroll
                for (int r = 0; r < 8; r++){
                    u64 ap = pack2(a[r], a[r]);
                    acc[r][0] = fma2(ap, b0, acc[r][0]);
                    acc[r][1] = fma2(ap, b1, acc[r][1]);
                    acc[r][2] = fma2(ap, b2, acc[r][2]);
                    acc[r][3] = fma2(ap, b3, acc[r][3]);
                }
            }
        }
        // store L * d2 (packed) -> sLp[i][k]
        #pragma unroll
        for (int r = 0; r < 8; r++)
            #pragma unroll
            for (int c = 0; c < 4; c++)
                sLp[(ty*8+r)*68 + tx*4 + c] = mul2(acc[r][c], sd2p[tx*4 + c]);
    }

    // ================= GEMM2 + fused trace =================
    u64 part = 0ull;
    {
        float* sW2t = sU;                   // [l][k] stride 68
        u64*   sWdp = (u64*)(sU + JCH*68);  // [l][i] packed, stride 128

        u64 acc2[4][8];
        #pragma unroll
        for (int kc = 0; kc < 4; kc++)
            #pragma unroll
            for (int ir = 0; ir < 8; ir++) acc2[kc][ir] = 0ull;

        int gk = tid >> 2;          // k 0..63
        int gl = (tid & 3) * 8;     // l base
        int hl = tid >> 3;          // l 0..31
        int hi = (tid & 7) * 16;    // i base

        for (int l0 = 0; l0 < 896; l0 += JCH){
            __syncthreads();
            // W2 tile transposed: sW2t[l][k] = W2[kt+k][l0+l]
            {
                const float* src = &gw2[(kt+gk)*896 + l0 + gl];
                float4 v0 = *(const float4*)src;
                float4 v1 = *(const float4*)(src + 4);
                sW2t[(gl+0)*68 + gk] = v0.x;
                sW2t[(gl+1)*68 + gk] = v0.y;
                sW2t[(gl+2)*68 + gk] = v0.z;
                sW2t[(gl+3)*68 + gk] = v0.w;
                sW2t[(gl+4)*68 + gk] = v1.x;
                sW2t[(gl+5)*68 + gk] = v1.y;
                sW2t[(gl+6)*68 + gk] = v1.z;
                sW2t[(gl+7)*68 + gk] = v1.w;
            }
            // Wd tile with d3 folded, packed
            {
                u64 d3p = pack2(g_d3[bA*896 + l0 + hl], g_d3[bB*896 + l0 + hl]);
                const float* src = &gdw[(l0+hl)*128 + hi];
                u64* dst = &sWdp[hl*128 + hi];
                #pragma unroll
                for (int q = 0; q < 4; q++){
                    float4 v = *(const float4*)(src + q*4);
                    dst[q*4+0] = mul2(pack2(v.x, v.x), d3p);
                    dst[q*4+1] = mul2(pack2(v.y, v.y), d3p);
                    dst[q*4+2] = mul2(pack2(v.z, v.z), d3p);
                    dst[q*4+3] = mul2(pack2(v.w, v.w), d3p);
                }
            }
            __syncthreads();
            #pragma unroll 8
            for (int ll = 0; ll < JCH; ll++){
                float4 av = *(const float4*)&sW2t[ll*68 + tx*4];
                const u64* bpp = &sWdp[ll*128 + ty*8];
                u64 b[8];
                #pragma unroll
                for (int ir = 0; ir < 8; ir++) b[ir] = bpp[ir];
                float a[4] = {av.x, av.y, av.z, av.w};
                #pragma unroll
                for (int kc = 0; kc < 4; kc++){
                    u64 ap = pack2(a[kc], a[kc]);
                    #pragma unroll
                    for (int ir = 0; ir < 8; ir++)
                        acc2[kc][ir] = fma2(ap, b[ir], acc2[kc][ir]);
                }
            }
        }
        // pair acc2[kc][ir] = R[k=tx*4+kc][i=ty*8+ir] with sLp[i][k] (d2 folded).
        // Row i=127 of L is exactly zero, so the out-of-range trace term vanishes.
        #pragma unroll
        for (int kc = 0; kc < 4; kc++)
            #pragma unroll
            for (int ir = 0; ir < 8; ir++)
                part = fma2(acc2[kc][ir], sLp[(ty*8+ir)*68 + tx*4 + kc], part);
    }

    float2 pv = unpack2(part);
    #pragma unroll
    for (int off = 16; off > 0; off >>= 1){
        pv.x += __shfl_xor_sync(0xffffffffu, pv.x, off);
        pv.y += __shfl_xor_sync(0xffffffffu, pv.y, off);
    }
    if ((tid & 31) == 0) swp[tid >> 5] = pack2(pv.x, pv.y);
    __syncthreads();
    if (tid == 0){
        float sA = 0.f, sB = 0.f;
        #pragma unroll
        for (int w = 0; w < 8; w++){ float2 v = unpack2(swp[w]); sA += v.x; sB += v.y; }
        atomicAdd(&g_tr[bA], sA);
        atomicAdd(&g_tr[bB], sB);
    }
}

// ---------------- finalize: dp_dt = g - p * tr ----------------
__global__ void fin_kernel(const float* __restrict__ p, float* __restrict__ out_dp)
{
    int b = blockIdx.x * blockDim.x + threadIdx.x;
    if (b < BSZ) out_dp[b] = g_gv[b] - p[b] * g_tr[b];
}

// ---------------- launch ----------------
extern "C" void kernel_launch(void* const* d_in, const int* in_sizes, int n_in,
                              void* d_out, int out_size)
{
    const float* pt  = (const float*)d_in[0];
    const float* x   = (const float*)d_in[1];
    // d_in[2] = g_x (unused by reference)
    const float* p   = (const float*)d_in[3];
    const float* gw0 = (const float*)d_in[4];
    const float* gb0 = (const float*)d_in[5];
    const float* gw1 = (const float*)d_in[6];
    const float* gb1 = (const float*)d_in[7];
    const float* gw2 = (const float*)d_in[8];
    const float* gb2 = (const float*)d_in[9];
    const float* gdw = (const float*)d_in[10];
    const float* gdb = (const float*)d_in[11];
    const float* bw0 = (const float*)d_in[12];
    const float* bb0 = (const float*)d_in[13];
    const float* bw1 = (const float*)d_in[14];
    const float* bb1 = (const float*)d_in[15];
    const float* bdw = (const float*)d_in[16];
    const float* bdb = (const float*)d_in[17];
    float* out = (float*)d_out;

    float *pX1, *pXB, *ph1, *pd1, *ph2, *pd2, *ph3, *pd3, *pe1, *pe2;
    cudaGetSymbolAddress((void**)&pX1, g_X1);
    cudaGetSymbolAddress((void**)&pXB, g_XB);
    cudaGetSymbolAddress((void**)&ph1, g_h1);
    cudaGetSymbolAddress((void**)&pd1, g_d1);
    cudaGetSymbolAddress((void**)&ph2, g_h2);
    cudaGetSymbolAddress((void**)&pd2, g_d2);
    cudaGetSymbolAddress((void**)&ph3, g_h3);
    cudaGetSymbolAddress((void**)&pd3, g_d3);
    cudaGetSymbolAddress((void**)&pe1, g_e1);
    cudaGetSymbolAddress((void**)&pe2, g_e2);

    static int smem_set = 0;
    if (!smem_set){
        cudaFuncSetAttribute(jac2_kernel, cudaFuncAttributeMaxDynamicSharedMemorySize, SMEM_JAC);
        smem_set = 1;
    }

    prep_kernel<<<BSZ, 256>>>(pt, x);
    // grn forward (stores h and d = 1 - h^2)
    fwd_gemm<true ><<<dim3(16, 16), 256>>>(pX1, 128,  gw0, gb0, ph1, pd1, 1024, 128);
    fwd_gemm<true ><<<dim3(15, 16), 256>>>(ph1, 1024, gw1, gb1, ph2, pd2, 960,  1024);
    fwd_gemm<true ><<<dim3(14, 16), 256>>>(ph2, 960,  gw2, gb2, ph3, pd3, 896,  960);
    fwd_gemm<false><<<dim3(2,  16), 256>>>(ph3, 896,  gdw, gdb, out, nullptr, 128, 896);
    // b-net forward
    fwd_gemm<true ><<<dim3(8,  16), 256>>>(pXB, 129,  bw0, bb0, pe1, nullptr, 512, 129);
    fwd_gemm<true ><<<dim3(7,  16), 256>>>(pe1, 512,  bw1, bb1, pe2, nullptr, 448, 512);
    bnet_head<<<BSZ, 128>>>(bdw, bdb, out + BSZ*128);
    // Jacobian trace (dominant cost) — packed f32x2, 2 samples per CTA
    jac2_kernel<<<dim3(BSZ/2, 15), 256, SMEM_JAC>>>(gw0, gw1, gw2, gdw);
    fin_kernel<<<4, 256>>>(p, out + BSZ*128 + BSZ);
}

// round 6
// speedup vs baseline: 3.2047x; 2.0657x over previous
#include <cuda_runtime.h>
#include <cuda_bf16.h>
#include <math.h>

#define BSZ 1024
typedef unsigned long long u64;
typedef unsigned int u32;

// ---------------- scratch (device globals; no allocations allowed) ----------------
__device__ float g_X1[BSZ*128];
__device__ float g_XB[BSZ*129];
__device__ float g_h1[BSZ*1024];
__device__ float g_d1[BSZ*1024];
__device__ float g_h2[BSZ*960];
__device__ float g_d2[BSZ*960];
__device__ float g_h3[BSZ*896];
__device__ float g_d3[BSZ*896];
__device__ float g_e1[BSZ*512];
__device__ float g_e2[BSZ*448];
__device__ float g_gv[BSZ];
__device__ float g_tr[BSZ];

// fixed operands prepared once per launch
__device__ float        g_W1t[1024*1024];       // [k][j] = W1[j][k], rows k>=960 zero
__device__ __nv_bfloat16 g_W0s_hi[128*1024];    // [i][j] = W0[i+1][j], row 127 zero (hi)
__device__ __nv_bfloat16 g_W0s_lo[128*1024];    // (lo residual)
__device__ __nv_bfloat16 g_Wdt_hi[128*896];     // [i][l] = Wd[l][i] (hi)
__device__ __nv_bfloat16 g_Wdt_lo[128*896];     // (lo residual)

// ---------------- helpers ----------------
__device__ __forceinline__ u32 smem_u32(const void* p){
    u32 a; asm("{ .reg .u64 t; cvta.to.shared.u64 t, %1; cvt.u32.u64 %0, t; }" : "=r"(a) : "l"(p));
    return a;
}
__device__ __forceinline__ void ldsm4(u32* r, u32 addr){
    asm volatile("ldmatrix.sync.aligned.m8n8.x4.shared.b16 {%0,%1,%2,%3}, [%4];"
        : "=r"(r[0]), "=r"(r[1]), "=r"(r[2]), "=r"(r[3]) : "r"(addr));
}
__device__ __forceinline__ void mma_bf16(float* c, const u32* a, const u32* b){
    asm volatile("mma.sync.aligned.m16n8k16.row.col.f32.bf16.bf16.f32 "
        "{%0,%1,%2,%3}, {%4,%5,%6,%7}, {%8,%9}, {%0,%1,%2,%3};"
        : "+f"(c[0]), "+f"(c[1]), "+f"(c[2]), "+f"(c[3])
        : "r"(a[0]), "r"(a[1]), "r"(a[2]), "r"(a[3]), "r"(b[0]), "r"(b[1]));
}
__device__ __forceinline__ void cpasync16(u32 dst, const void* src){
    asm volatile("cp.async.cg.shared.global [%0], [%1], 16;" :: "r"(dst), "l"(src));
}

// ---------------- prep: build inputs, zero trace accumulators ----------------
__global__ void prep_kernel(const float* __restrict__ pt, const float* __restrict__ x)
{
    int b = blockIdx.x;
    int t = threadIdx.x;
    float tv = pt[0];
    if (t == 0){ g_X1[b*128] = tv; g_XB[b*129] = tv; g_tr[b] = 0.f; }
    for (int c = t; c < 128; c += blockDim.x){
        float xv = x[b*128 + c];
        if (c < 127) g_X1[b*128 + 1 + c] = xv;
        g_XB[b*129 + 1 + c] = xv;
    }
}

// ---------------- prep: fixed-operand transposes + bf16 hi/lo splits ----------------
__global__ void prep_wt(const float* __restrict__ gw0, const float* __restrict__ gw1,
                        const float* __restrict__ gdw)
{
    int stride = gridDim.x * blockDim.x;
    int t0 = blockIdx.x * blockDim.x + threadIdx.x;
    for (int idx = t0; idx < 1024*1024; idx += stride){
        int k = idx >> 10, j = idx & 1023;
        g_W1t[idx] = (k < 960) ? gw1[j*960 + k] : 0.f;
    }
    for (int idx = t0; idx < 128*1024; idx += stride){
        int i = idx >> 10, j = idx & 1023;
        float v = (i < 127) ? gw0[(i+1)*1024 + j] : 0.f;
        __nv_bfloat16 h = __float2bfloat16_rn(v);
        g_W0s_hi[idx] = h;
        g_W0s_lo[idx] = __float2bfloat16_rn(v - __bfloat162float(h));
    }
    for (int idx = t0; idx < 128*896; idx += stride){
        int i = idx / 896, l = idx - i*896;
        float v = gdw[l*128 + i];
        __nv_bfloat16 h = __float2bfloat16_rn(v);
        g_Wdt_hi[idx] = h;
        g_Wdt_lo[idx] = __float2bfloat16_rn(v - __bfloat162float(h));
    }
}

// ---------------- generic fp32 GEMM: C = act(A @ W + bias), M=1024 ----------------
template<bool TANH>
__global__ __launch_bounds__(256)
void fwd_gemm(const float* __restrict__ A, int lda,
              const float* __restrict__ W,
              const float* __restrict__ bias,
              float* __restrict__ H, float* __restrict__ Dm,
              int N, int K)
{
    __shared__ float sA[16*65];
    __shared__ float sB[16*64];
    int n0 = blockIdx.x * 64;
    int m0 = blockIdx.y * 64;
    int tid = threadIdx.x;
    int tx = tid & 15, ty = tid >> 4;
    float acc[4][4] = {};
    for (int k0 = 0; k0 < K; k0 += 16){
        #pragma unroll
        for (int e = 0; e < 4; e++){
            int id = tid + e*256;
            int m = id >> 4, k = id & 15;
            sA[k*65 + m] = (k0 + k < K) ? A[(m0+m)*lda + k0 + k] : 0.f;
        }
        #pragma unroll
        for (int e = 0; e < 4; e++){
            int id = tid + e*256;
            int kb = id >> 6, n = id & 63;
            sB[kb*64 + n] = (k0 + kb < K) ? W[(k0+kb)*N + n0 + n] : 0.f;
        }
        __syncthreads();
        #pragma unroll
        for (int kk = 0; kk < 16; kk++){
            float a[4], bb[4];
            #pragma unroll
            for (int r = 0; r < 4; r++) a[r] = sA[kk*65 + ty*4 + r];
            #pragma unroll
            for (int c = 0; c < 4; c++) bb[c] = sB[kk*64 + tx*4 + c];
            #pragma unroll
            for (int r = 0; r < 4; r++)
                #pragma unroll
                for (int c = 0; c < 4; c++)
                    acc[r][c] += a[r]*bb[c];
        }
        __syncthreads();
    }
    #pragma unroll
    for (int r = 0; r < 4; r++){
        int m = m0 + ty*4 + r;
        #pragma unroll
        for (int c = 0; c < 4; c++){
            int n = n0 + tx*4 + c;
            float v = acc[r][c] + bias[n];
            if (TANH){
                float h = tanhf(v);
                H[m*N + n] = h;
                if (Dm) Dm[m*N + n] = 1.f - h*h;
            } else {
                H[m*N + n] = v;
            }
        }
    }
}

// ---------------- b-net head ----------------
__global__ void bnet_head(const float* __restrict__ bdw, const float* __restrict__ bdb,
                          float* __restrict__ out_g)
{
    int b = blockIdx.x;
    int t = threadIdx.x;
    float s = 0.f;
    for (int k = t; k < 448; k += 128) s += g_e2[b*448 + k] * bdw[k];
    #pragma unroll
    for (int off = 16; off > 0; off >>= 1) s += __shfl_xor_sync(0xffffffffu, s, off);
    __shared__ float sw[4];
    if ((t & 31) == 0) sw[t >> 5] = s;
    __syncthreads();
    if (t == 0){
        float g = sw[0] + sw[1] + sw[2] + sw[3] + bdb[0];
        g_gv[b] = g;
        out_g[b] = g;
    }
}

// ---------------- Jacobian trace: mma.sync bf16x3 ----------------
// CTA = (sample b, k-tile ktb of 128 over 960-pad-1024).
// GEMM1: LT[k,i] = sum_j (W1t[ktb+k][j]*d1[j]) * W0s[i][j]   kdim j=1024 (16 chunks)
// GEMM2: R [k,i] = sum_l (W2[ktb+k][l]*d3[l])  * Wdt[i][l]   kdim l=896  (14 chunks)
// tr += sum LT[k,i]*d2[ktb+k]*R[k,i]  — both accs share (k,i) register layout.
#define JSTRB   144          // smem row stride bytes (72 bf16)
#define OA_HI   0            // folded-A hi tile [128][72]
#define OA_LO   18432        // folded-A lo tile
#define OB_BASE 36864        // fixed-B double buffer: [2][hi+lo][128][72]
#define OB_SIZE 36864
#define SMEM_JM (OB_BASE + 2*OB_SIZE)   // 110592 bytes

__device__ __forceinline__ void load_A(float (&e)[32], const float* gsrc, int rstride,
                                       int c0, const float* dvec, bool ok, int r, int jb)
{
    if (ok){
        const float* src = gsrc + (long)r*rstride + c0 + jb;
        const float* ds  = dvec + c0 + jb;
        #pragma unroll
        for (int g = 0; g < 8; g++){
            float4 u = *(const float4*)(src + g*4);
            float4 d = *(const float4*)(ds  + g*4);
            e[g*4+0] = u.x*d.x; e[g*4+1] = u.y*d.y;
            e[g*4+2] = u.z*d.z; e[g*4+3] = u.w*d.w;
        }
    } else {
        #pragma unroll
        for (int q = 0; q < 32; q++) e[q] = 0.f;
    }
}

__device__ __forceinline__ void store_A(const float (&e)[32], char* smem, int r, int jb)
{
    char* dh = smem + OA_HI + r*JSTRB + jb*2;
    char* dl = smem + OA_LO + r*JSTRB + jb*2;
    #pragma unroll
    for (int g = 0; g < 4; g++){
        u32 h[4], l[4];
        #pragma unroll
        for (int q = 0; q < 4; q++){
            float x = e[g*8 + q*2], y = e[g*8 + q*2 + 1];
            __nv_bfloat162 hp = __floats2bfloat162_rn(x, y);
            h[q] = *reinterpret_cast<u32*>(&hp);
            float rx = x - __low2float(hp);
            float ry = y - __high2float(hp);
            __nv_bfloat162 lp = __floats2bfloat162_rn(rx, ry);
            l[q] = *reinterpret_cast<u32*>(&lp);
        }
        *(uint4*)(dh + g*16) = make_uint4(h[0], h[1], h[2], h[3]);
        *(uint4*)(dl + g*16) = make_uint4(l[0], l[1], l[2], l[3]);
    }
}

__device__ __forceinline__ void issue_B(const __nv_bfloat16* ghi, const __nv_bfloat16* glo,
                                        int rowlen, int c0, int p, u32 sb, int tid)
{
    #pragma unroll
    for (int q = 0; q < 8; q++){
        int e    = tid + q*256;
        int half = e >> 10;
        int r    = (e >> 3) & 127;
        int c16  = e & 7;
        const __nv_bfloat16* src = (half ? glo : ghi) + (long)r*rowlen + c0 + c16*8;
        u32 dst = sb + OB_BASE + p*OB_SIZE + half*18432 + r*JSTRB + c16*16;
        cpasync16(dst, src);
    }
    asm volatile("cp.async.commit_group;");
}

__device__ __forceinline__ void compute_chunk(float (&acc)[2][8][4], u32 sb, int p,
                                              int mw, int nw, int lane)
{
    u32 aH = sb + OA_HI + (u32)(mw + (lane & 15))*JSTRB + ((lane >> 4) * 8)*2;
    u32 aL = aH + (OA_LO - OA_HI);
    u32 bH = sb + OB_BASE + p*OB_SIZE
           + (u32)(nw + (lane & 7) + ((lane >> 4) << 3))*JSTRB
           + (((lane >> 3) & 1) * 8)*2;
    u32 bL = bH + 18432;
    #pragma unroll
    for (int kk = 0; kk < 4; kk++){
        int jo = kk*32;   // 16 bf16 = 32 bytes per k-step
        u32 ah[2][4], al[2][4], bh[4][4], bl[4][4];
        ldsm4(ah[0], aH + jo);
        ldsm4(ah[1], aH + 16*JSTRB + jo);
        #pragma unroll
        for (int n2 = 0; n2 < 4; n2++) ldsm4(bh[n2], bH + n2*16*JSTRB + jo);
        #pragma unroll
        for (int mt = 0; mt < 2; mt++)
            #pragma unroll
            for (int n2 = 0; n2 < 4; n2++){
                mma_bf16(acc[mt][n2*2],     ah[mt], &bh[n2][0]);
                mma_bf16(acc[mt][n2*2 + 1], ah[mt], &bh[n2][2]);
            }
        ldsm4(al[0], aL + jo);
        ldsm4(al[1], aL + 16*JSTRB + jo);
        #pragma unroll
        for (int mt = 0; mt < 2; mt++)
            #pragma unroll
            for (int n2 = 0; n2 < 4; n2++){
                mma_bf16(acc[mt][n2*2],     al[mt], &bh[n2][0]);
                mma_bf16(acc[mt][n2*2 + 1], al[mt], &bh[n2][2]);
            }
        #pragma unroll
        for (int n2 = 0; n2 < 4; n2++) ldsm4(bl[n2], bL + n2*16*JSTRB + jo);
        #pragma unroll
        for (int mt = 0; mt < 2; mt++)
            #pragma unroll
            for (int n2 = 0; n2 < 4; n2++){
                mma_bf16(acc[mt][n2*2],     ah[mt], &bl[n2][0]);
                mma_bf16(acc[mt][n2*2 + 1], ah[mt], &bl[n2][2]);
            }
    }
}

__global__ void __launch_bounds__(256) jac_mma(const float* __restrict__ gw2)
{
    extern __shared__ char smj[];
    u32 sb = smem_u32(smj);
    int tid = threadIdx.x, lane = tid & 31, w = tid >> 5;
    int b = blockIdx.x, ktb = blockIdx.y * 128;
    int mw = (w & 3) * 32, nw = (w >> 2) * 64;
    int r  = tid >> 1, jb = (tid & 1) * 32;

    float acc1[2][8][4], acc2[2][8][4];
    #pragma unroll
    for (int mt = 0; mt < 2; mt++)
        #pragma unroll
        for (int nt = 0; nt < 8; nt++)
            #pragma unroll
            for (int q = 0; q < 4; q++){ acc1[mt][nt][q] = 0.f; acc2[mt][nt][q] = 0.f; }

    // ===== GEMM1: LT = (W1t·diag(d1)) x W0s^T =====
    {
        const float* A1 = g_W1t + (long)ktb * 1024;
        const float* dv = g_d1 + (long)b * 1024;
        issue_B(g_W0s_hi, g_W0s_lo, 1024, 0, 0, sb, tid);
        #pragma unroll 1
        for (int c = 0; c < 16; c++){
            int p = c & 1;
            float e[32];
            load_A(e, A1, 1024, c*64, dv, true, r, jb);
            __syncthreads();
            store_A(e, smj, r, jb);
            if (c + 1 < 16){
                issue_B(g_W0s_hi, g_W0s_lo, 1024, (c+1)*64, p ^ 1, sb, tid);
                asm volatile("cp.async.wait_group 1;");
            } else {
                asm volatile("cp.async.wait_group 0;");
            }
            __syncthreads();
            compute_chunk(acc1, sb, p, mw, nw, lane);
        }
    }

    // fold d2 into acc1 (rows k >= 960 zeroed)
    #pragma unroll
    for (int mt = 0; mt < 2; mt++)
        #pragma unroll
        for (int s = 0; s < 2; s++){
            int kg = ktb + mw + mt*16 + (lane >> 2) + s*8;
            float d2v = (kg < 960) ? g_d2[(long)b*960 + kg] : 0.f;
            #pragma unroll
            for (int nt = 0; nt < 8; nt++){
                acc1[mt][nt][s*2]     *= d2v;
                acc1[mt][nt][s*2 + 1] *= d2v;
            }
        }

    // ===== GEMM2: R = (W2·diag(d3)) x Wdt^T =====
    {
        const float* A2 = gw2 + (long)ktb * 896;
        const float* dv = g_d3 + (long)b * 896;
        bool okrow = (ktb + r) < 960;
        issue_B(g_Wdt_hi, g_Wdt_lo, 896, 0, 0, sb, tid);
        #pragma unroll 1
        for (int c = 0; c < 14; c++){
            int p = c & 1;
            float e[32];
            load_A(e, A2, 896, c*64, dv, okrow, r, jb);
            __syncthreads();
            store_A(e, smj, r, jb);
            if (c + 1 < 14){
                issue_B(g_Wdt_hi, g_Wdt_lo, 896, (c+1)*64, p ^ 1, sb, tid);
                asm volatile("cp.async.wait_group 1;");
            } else {
                asm volatile("cp.async.wait_group 0;");
            }
            __syncthreads();
            compute_chunk(acc2, sb, p, mw, nw, lane);
        }
    }

    // ===== trace: register dot product (identical layouts) =====
    float part = 0.f;
    #pragma unroll
    for (int mt = 0; mt < 2; mt++)
        #pragma unroll
        for (int nt = 0; nt < 8; nt++)
            #pragma unroll
            for (int q = 0; q < 4; q++)
                part += acc1[mt][nt][q] * acc2[mt][nt][q];
    #pragma unroll
    for (int off = 16; off > 0; off >>= 1)
        part += __shfl_xor_sync(0xffffffffu, part, off);
    if (lane == 0) atomicAdd(&g_tr[b], part);
}

// ---------------- finalize ----------------
__global__ void fin_kernel(const float* __restrict__ p, float* __restrict__ out_dp)
{
    int b = blockIdx.x * blockDim.x + threadIdx.x;
    if (b < BSZ) out_dp[b] = g_gv[b] - p[b] * g_tr[b];
}

// ---------------- launch ----------------
extern "C" void kernel_launch(void* const* d_in, const int* in_sizes, int n_in,
                              void* d_out, int out_size)
{
    const float* pt  = (const float*)d_in[0];
    const float* x   = (const float*)d_in[1];
    const float* p   = (const float*)d_in[3];
    const float* gw0 = (const float*)d_in[4];
    const float* gb0 = (const float*)d_in[5];
    const float* gw1 = (const float*)d_in[6];
    const float* gb1 = (const float*)d_in[7];
    const float* gw2 = (const float*)d_in[8];
    const float* gb2 = (const float*)d_in[9];
    const float* gdw = (const float*)d_in[10];
    const float* gdb = (const float*)d_in[11];
    const float* bw0 = (const float*)d_in[12];
    const float* bb0 = (const float*)d_in[13];
    const float* bw1 = (const float*)d_in[14];
    const float* bb1 = (const float*)d_in[15];
    const float* bdw = (const float*)d_in[16];
    const float* bdb = (const float*)d_in[17];
    float* out = (float*)d_out;

    float *pX1, *pXB, *ph1, *pd1, *ph2, *pd2, *ph3, *pd3, *pe1, *pe2;
    cudaGetSymbolAddress((void**)&pX1, g_X1);
    cudaGetSymbolAddress((void**)&pXB, g_XB);
    cudaGetSymbolAddress((void**)&ph1, g_h1);
    cudaGetSymbolAddress((void**)&pd1, g_d1);
    cudaGetSymbolAddress((void**)&ph2, g_h2);
    cudaGetSymbolAddress((void**)&pd2, g_d2);
    cudaGetSymbolAddress((void**)&ph3, g_h3);
    cudaGetSymbolAddress((void**)&pd3, g_d3);
    cudaGetSymbolAddress((void**)&pe1, g_e1);
    cudaGetSymbolAddress((void**)&pe2, g_e2);

    static int smem_set = 0;
    if (!smem_set){
        cudaFuncSetAttribute(jac_mma, cudaFuncAttributeMaxDynamicSharedMemorySize, SMEM_JM);
        smem_set = 1;
    }

    prep_kernel<<<BSZ, 256>>>(pt, x);
    prep_wt<<<256, 256>>>(gw0, gw1, gdw);
    // grn forward (stores h and d = 1 - h^2)
    fwd_gemm<true ><<<dim3(16, 16), 256>>>(pX1, 128,  gw0, gb0, ph1, pd1, 1024, 128);
    fwd_gemm<true ><<<dim3(15, 16), 256>>>(ph1, 1024, gw1, gb1, ph2, pd2, 960,  1024);
    fwd_gemm<true ><<<dim3(14, 16), 256>>>(ph2, 960,  gw2, gb2, ph3, pd3, 896,  960);
    fwd_gemm<false><<<dim3(2,  16), 256>>>(ph3, 896,  gdw, gdb, out, nullptr, 128, 896);
    // b-net forward
    fwd_gemm<true ><<<dim3(8,  16), 256>>>(pXB, 129,  bw0, bb0, pe1, nullptr, 512, 129);
    fwd_gemm<true ><<<dim3(7,  16), 256>>>(pe1, 512,  bw1, bb1, pe2, nullptr, 448, 512);
    bnet_head<<<BSZ, 128>>>(bdw, bdb, out + BSZ*128);
    // Jacobian trace — warp-level bf16x3 tensor cores
    jac_mma<<<dim3(BSZ, 8), 256, SMEM_JM>>>(gw2);
    fin_kernel<<<4, 256>>>(p, out + BSZ*128 + BSZ);
}